// round 4
// baseline (speedup 1.0000x reference)
#include <cuda_runtime.h>

#define CAPN 134
#define SEQN 144
#define INVN 16
#define ESP  1072
#define EFT  64
#define BZN  32

typedef unsigned long long ull;

// ---------------- packed f32x2 helpers (Blackwell FFMA2 path) ----------------
__device__ __forceinline__ ull dup2(float v) {
    ull r; asm("mov.b64 %0, {%1, %1};" : "=l"(r) : "f"(v)); return r;
}
__device__ __forceinline__ void fma2(ull& d, ull a, ull b) {
    asm("fma.rn.f32x2 %0, %1, %2, %0;" : "+l"(d) : "l"(a), "l"(b));
}
__device__ __forceinline__ ull add2(ull a, ull b) {
    ull r; asm("add.rn.f32x2 %0, %1, %2;" : "=l"(r) : "l"(a), "l"(b)); return r;
}
__device__ __forceinline__ ull mul2p(ull a, ull b) {
    ull r; asm("mul.rn.f32x2 %0, %1, %2;" : "=l"(r) : "l"(a), "l"(b)); return r;
}

// ---------------- device-global precomputed tables (tiny) ----------------
__device__ int   g_rowptr[CAPN + 1];
__device__ int   g_cols[ESP];
__device__ float g_invdeg[CAPN];
__device__ float g_M1[256], g_M2[256], g_B1[256], g_B2[256];
__device__ float g_Wt[16 * 5 * 16];     // [i][k][j]
__device__ float g_bias[SEQN * 16];     // [s][j]

// ---------------- prep: CSR + composite weights ----------------
__global__ void prep_kernel(const int* __restrict__ ge, const int* __restrict__ fe,
                            const float* __restrict__ gWl, const float* __restrict__ gbl,
                            const float* __restrict__ gWr,
                            const float* __restrict__ fbl,
                            const float* __restrict__ c1w, const float* __restrict__ c2w,
                            const float* __restrict__ fcw, const float* __restrict__ fcb)
{
    __shared__ int   cnt[CAPN];
    __shared__ int   base[CAPN + 1];
    __shared__ int   fill[CAPN];
    __shared__ int   fcnt[256];
    __shared__ int   fdeg[INVN];
    __shared__ float Afn[256];
    int tid = threadIdx.x;

    if (tid < CAPN) cnt[tid] = 0;
    if (tid < 256)  fcnt[tid] = 0;
    if (tid < INVN) fdeg[tid] = 0;
    __syncthreads();

    for (int e = tid; e < ESP; e += blockDim.x) atomicAdd(&cnt[ge[ESP + e]], 1);
    for (int e = tid; e < EFT; e += blockDim.x) {
        int d = fe[EFT + e], s = fe[e];
        atomicAdd(&fcnt[d * INVN + s], 1);
        atomicAdd(&fdeg[d], 1);
    }
    __syncthreads();

    if (tid == 0) {
        int run = 0;
        for (int i = 0; i < CAPN; i++) { base[i] = run; run += cnt[i]; }
        base[CAPN] = run;
    }
    __syncthreads();
    if (tid < CAPN) fill[tid] = base[tid];
    __syncthreads();
    for (int e = tid; e < ESP; e += blockDim.x) {
        int d = ge[ESP + e];
        int pos = atomicAdd(&fill[d], 1);
        g_cols[pos] = ge[e];
    }
    if (tid < CAPN)  g_invdeg[tid] = 1.0f / fmaxf((float)cnt[tid], 1.0f);
    if (tid <= CAPN) g_rowptr[tid] = base[tid];
    if (tid < 256) {
        int i = tid >> 4;
        Afn[tid] = (float)fcnt[tid] / fmaxf((float)fdeg[i], 1.0f);
    }
    __syncthreads();

    if (tid < 256) {
        int i = tid >> 4, j = tid & 15;
        float m1 = 0.f, m2 = 0.f, b1 = 0.f;
        for (int o = 0; o < 16; o++) {
            m1 += gWl[i * 16 + o] * fcw[o * 16 + j];
            m2 += gWr[i * 16 + o] * fcw[o * 16 + j];
            b1 += Afn[o * 16 + i] * fcw[(16 + o) * 16 + j];
        }
        g_M1[tid] = m1; g_M2[tid] = m2; g_B1[tid] = b1;
        g_B2[tid] = fcw[(16 + i) * 16 + j];
        for (int k = 0; k < 5; k++) {
            float wt = 0.f;
            for (int o = 0; o < 16; o++) {
                float wm = c2w[(o * 16 + i) * 5 + k];
                if (k >= 1 && k <= 3) wm += c1w[(o * 16 + i) * 3 + (k - 1)];
                wt += wm * fcw[(32 + o) * 16 + j];
            }
            g_Wt[(i * 5 + k) * 16 + j] = wt;
        }
    }
    for (int idx = tid; idx < SEQN * 16; idx += blockDim.x) {
        int s = idx >> 4, j = idx & 15;
        float cs = 0.f, gb = 0.f;
        for (int i = 0; i < 16; i++) cs += fcw[(16 + i) * 16 + j];
        for (int o = 0; o < 16; o++) gb += gbl[o] * fcw[o * 16 + j];
        g_bias[idx] = fcb[j] + fbl[s] * cs + gb;
    }
}

// ---------------- fused main kernel: 2 items/block, 2 CTAs/SM ----------------
#define TS 20
struct SM {
    float tile[2][SEQN + 4][TS];   // 23,680 B (rows 0,1,146,147 zero pad)
    float macc[2][SEQN][TS];       // 23,040 B
    float P[2][2][SEQN][16];       // 36,864 B
    float WT[2][SEQN][4];          // 4,608 B  (transposed W chunk, 16B rows)
    float M1[256], M2[256], B1[256], B2[256];  // 4,096 B
    float Wt[16 * 5 * 16];         // 5,120 B
    float bias[SEQN][16];          // 9,216 B
};                                 // total 106,624 B -> 2 CTAs/SM

__global__ void __launch_bounds__(288, 2)
main_kernel(const float* __restrict__ src,
            const float* __restrict__ fWl, const float* __restrict__ fWr,
            float* __restrict__ out)
{
    extern __shared__ SM smx[];
    SM& s = smx[0];
    const int tid = threadIdx.x;
    const int item0 = blockIdx.x * 2;

    // ---- phase 0: stage constants ----
    if (tid < 256) {
        s.M1[tid] = g_M1[tid]; s.M2[tid] = g_M2[tid];
        s.B1[tid] = g_B1[tid]; s.B2[tid] = g_B2[tid];
    }
    for (int idx = tid; idx < 16 * 5 * 16; idx += 288) s.Wt[idx] = g_Wt[idx];
    for (int idx = tid; idx < SEQN * 16; idx += 288)
        s.bias[idx >> 4][idx & 15] = g_bias[idx];

    // ---- phase 1: zero pads + load 2 tiles ----
    for (int idx = tid; idx < 2 * 4 * TS; idx += 288) {
        int it = idx / (4 * TS); int rr = idx % (4 * TS);
        int pr = rr / TS, cc = rr % TS;
        int row = (pr < 2) ? pr : (SEQN + pr);
        s.tile[it][row][cc] = 0.f;
    }
    for (int idx = tid; idx < 2 * SEQN * 4; idx += 288) {
        int it = idx / (SEQN * 4);
        int rr = idx % (SEQN * 4);
        int ss = rr >> 2, iq = (rr & 3) * 4;
        *(float4*)&s.tile[it][ss + 2][iq] =
            *(const float4*)(src + ((size_t)(item0 + it) * SEQN + ss) * 16 + iq);
    }
    __syncthreads();

    // ---- phase 2: spatial neighbor-mean gather (288 thr = 2 x 144) ----
    {
        int it = tid / SEQN, ss = tid % SEQN;
        int item = item0 + it;
        int b = item / CAPN, c = item % CAPN;
        ull accp[8];
        #pragma unroll
        for (int q = 0; q < 8; q++) accp[q] = 0ull;
        int p0 = g_rowptr[c], p1e = g_rowptr[c + 1];
        for (int p = p0; p < p1e; p++) {
            int cp = g_cols[p];
            const ulonglong2* row =
                (const ulonglong2*)(src + ((size_t)(b * CAPN + cp) * SEQN + ss) * 16);
            ulonglong2 r0 = row[0], r1 = row[1], r2 = row[2], r3 = row[3];
            accp[0] = add2(accp[0], r0.x); accp[1] = add2(accp[1], r0.y);
            accp[2] = add2(accp[2], r1.x); accp[3] = add2(accp[3], r1.y);
            accp[4] = add2(accp[4], r2.x); accp[5] = add2(accp[5], r2.y);
            accp[6] = add2(accp[6], r3.x); accp[7] = add2(accp[7], r3.y);
        }
        ull scd = dup2(g_invdeg[c]);
        #pragma unroll
        for (int qq = 0; qq < 4; qq++)
            *(ulonglong2*)&s.macc[it][ss][qq * 4] =
                make_ulonglong2(mul2p(accp[2 * qq], scd), mul2p(accp[2 * qq + 1], scd));
    }

    // ---- phase 3: P1 = tile@B1, P2 = tile@B2 (288 thr = 2 x 144 rows) ----
    {
        int it = tid / SEQN, t = tid % SEQN;
        float x[16];
        #pragma unroll
        for (int iq = 0; iq < 16; iq += 4) {
            float4 v = *(const float4*)&s.tile[it][t + 2][iq];
            x[iq] = v.x; x[iq + 1] = v.y; x[iq + 2] = v.z; x[iq + 3] = v.w;
        }
        ull pp1[8], pp2[8];
        #pragma unroll
        for (int q = 0; q < 8; q++) { pp1[q] = 0ull; pp2[q] = 0ull; }
        #pragma unroll
        for (int i = 0; i < 16; i++) {
            ull xd = dup2(x[i]);
            #pragma unroll
            for (int qq = 0; qq < 4; qq++) {
                ulonglong2 b1 = *(const ulonglong2*)&s.B1[i * 16 + qq * 4];
                ulonglong2 b2 = *(const ulonglong2*)&s.B2[i * 16 + qq * 4];
                fma2(pp1[2 * qq], xd, b1.x); fma2(pp1[2 * qq + 1], xd, b1.y);
                fma2(pp2[2 * qq], xd, b2.x); fma2(pp2[2 * qq + 1], xd, b2.y);
            }
        }
        #pragma unroll
        for (int qq = 0; qq < 4; qq++) {
            *(ulonglong2*)&s.P[it][0][t][qq * 4] = make_ulonglong2(pp1[2 * qq], pp1[2 * qq + 1]);
            *(ulonglong2*)&s.P[it][1][t][qq * 4] = make_ulonglong2(pp2[2 * qq], pp2[2 * qq + 1]);
        }
    }
    __syncthreads();

    // ---- phase 4: per-thread 1 item x 4 rows x 4 j (2 packed pairs) ----
    const int it = tid / 144;
    const int r  = tid % 144;
    const int jg = r / 36, sg = r % 36;
    const int j0 = jg * 4;
    int srow[4];
    #pragma unroll
    for (int a = 0; a < 4; a++) srow[a] = sg + 36 * a;

    ull acc2[4][2];
    #pragma unroll
    for (int a = 0; a < 4; a++) {
        ulonglong2 bv = *(const ulonglong2*)&s.bias[srow[a]][j0];
        ulonglong2 tv = *(const ulonglong2*)&s.tile[it][srow[a] + 2][j0];
        acc2[a][0] = add2(bv.x, tv.x);
        acc2[a][1] = add2(bv.y, tv.y);
    }

    // spatial: macc@M1 + tile@M2
    #pragma unroll 1
    for (int iq = 0; iq < 16; iq += 4) {
        ulonglong2 m1p[4], m2p[4];
        #pragma unroll
        for (int ii = 0; ii < 4; ii++) {
            m1p[ii] = *(const ulonglong2*)&s.M1[(iq + ii) * 16 + j0];
            m2p[ii] = *(const ulonglong2*)&s.M2[(iq + ii) * 16 + j0];
        }
        #pragma unroll
        for (int a = 0; a < 4; a++) {
            float4 tv = *(const float4*)&s.tile[it][srow[a] + 2][iq];
            float4 mv = *(const float4*)&s.macc[it][srow[a]][iq];
            float tvv[4], mvv[4];
            *(float4*)tvv = tv; *(float4*)mvv = mv;
            #pragma unroll
            for (int ii = 0; ii < 4; ii++) {
                ull td = dup2(tvv[ii]), md = dup2(mvv[ii]);
                fma2(acc2[a][0], td, m2p[ii].x); fma2(acc2[a][1], td, m2p[ii].y);
                fma2(acc2[a][0], md, m1p[ii].x); fma2(acc2[a][1], md, m1p[ii].y);
            }
        }
    }

    // temporal: merged width-5 conv, zero-padded rows
    #pragma unroll 1
    for (int k = 0; k < 5; k++) {
        #pragma unroll 1
        for (int iq = 0; iq < 16; iq += 4) {
            ulonglong2 wtp[4];
            #pragma unroll
            for (int ii = 0; ii < 4; ii++)
                wtp[ii] = *(const ulonglong2*)&s.Wt[((iq + ii) * 5 + k) * 16 + j0];
            #pragma unroll
            for (int a = 0; a < 4; a++) {
                float4 tv = *(const float4*)&s.tile[it][srow[a] + k][iq];
                float tvv[4];
                *(float4*)tvv = tv;
                #pragma unroll
                for (int ii = 0; ii < 4; ii++) {
                    ull td = dup2(tvv[ii]);
                    fma2(acc2[a][0], td, wtp[ii].x); fma2(acc2[a][1], td, wtp[ii].y);
                }
            }
        }
    }

    // feature seq-mix: acc[s,j] += sum_t Wl[t,s]*P1[t,j] + Wr[t,s]*P2[t,j]
    #pragma unroll 1
    for (int tc = 0; tc < SEQN; tc += 4) {
        __syncthreads();
        for (int q = tid; q < 1152; q += 288) {
            int w = q / 576, rr2 = q % 576;
            int tt = rr2 / SEQN, ss = rr2 % SEQN;
            const float* Wg = w ? fWr : fWl;
            s.WT[w][ss][tt] = Wg[(tc + tt) * SEQN + ss];     // transpose into 16B rows
        }
        __syncthreads();
        float wl[4][4], wr[4][4];
        #pragma unroll
        for (int a = 0; a < 4; a++) {
            *(float4*)wl[a] = *(const float4*)&s.WT[0][srow[a]][0];
            *(float4*)wr[a] = *(const float4*)&s.WT[1][srow[a]][0];
        }
        #pragma unroll
        for (int tt = 0; tt < 4; tt++) {
            const int t = tc + tt;
            ulonglong2 p1 = *(const ulonglong2*)&s.P[it][0][t][j0];
            ulonglong2 p2 = *(const ulonglong2*)&s.P[it][1][t][j0];
            #pragma unroll
            for (int a = 0; a < 4; a++) {
                ull wld = dup2(wl[a][tt]);
                ull wrd = dup2(wr[a][tt]);
                fma2(acc2[a][0], wld, p1.x); fma2(acc2[a][1], wld, p1.y);
                fma2(acc2[a][0], wrd, p2.x); fma2(acc2[a][1], wrd, p2.y);
            }
        }
    }

    // ---- write out (packed stores) ----
    const size_t obase = (size_t)(item0 + it) * SEQN * 16;
    #pragma unroll
    for (int a = 0; a < 4; a++)
        *(ulonglong2*)(out + obase + (size_t)srow[a] * 16 + j0) =
            make_ulonglong2(acc2[a][0], acc2[a][1]);
}

// ---------------- launch ----------------
extern "C" void kernel_launch(void* const* d_in, const int* in_sizes, int n_in,
                              void* d_out, int out_size)
{
    const float* src = (const float*)d_in[0];
    const int*   ge  = (const int*)d_in[1];
    const int*   fe  = (const int*)d_in[2];
    const float* gWl = (const float*)d_in[3];
    const float* gbl = (const float*)d_in[4];
    const float* gWr = (const float*)d_in[5];
    const float* fWl = (const float*)d_in[6];
    const float* fbl = (const float*)d_in[7];
    const float* fWr = (const float*)d_in[8];
    const float* c1w = (const float*)d_in[9];
    const float* c2w = (const float*)d_in[10];
    const float* fcw = (const float*)d_in[11];
    const float* fcb = (const float*)d_in[12];
    float* out = (float*)d_out;

    cudaFuncSetAttribute(main_kernel, cudaFuncAttributeMaxDynamicSharedMemorySize,
                         (int)sizeof(SM));

    prep_kernel<<<1, 256>>>(ge, fe, gWl, gbl, gWr, fbl, c1w, c2w, fcw, fcb);
    main_kernel<<<(BZN * CAPN) / 2, 288, sizeof(SM)>>>(src, fWl, fWr, out);
}